// round 2
// baseline (speedup 1.0000x reference)
#include <cuda_runtime.h>
#include <cstdint>

// LengthTransform, round 2: windowed softmax + union-window register accumulation.
// Kernel A (prep): per-batch r = src_len/tgt_len, i2 = 1/(2 ls^2), tl.
// Kernel B (main): warp owns 4 consecutive t's; computes their 32-wide softmax
// windows, then sweeps the UNION of the 4 windows once, loading each x row a
// single time and FMA-ing into 4 accumulator pairs with zero-padded weights.
// No __syncthreads anywhere in kernel B.

#define TT       16    // t-values per block (4 warps x 4 t)
#define NTH_B    128

__device__ float4 g_params[1024];   // {r, i2, tl_f, 0} per batch

__global__ void lt_prep(const float* __restrict__ mask,
                        const float* __restrict__ ls_ptr,
                        const int*   __restrict__ tgt_lens,
                        int B, int S)
{
    const int b    = blockIdx.x;
    const int tid  = threadIdx.x;
    const int lane = tid & 31;
    const int wid  = tid >> 5;
    __shared__ float red[8];

    float part = 0.f;
    const int S4 = S >> 2;
    const float4* m4 = (const float4*)(mask + (size_t)b * S);
    for (int i = tid; i < S4; i += 256) {
        float4 v = m4[i];
        part += (v.x + v.y) + (v.z + v.w);
    }
    for (int i = (S4 << 2) + tid; i < S; i += 256) part += mask[(size_t)b * S + i];
    #pragma unroll
    for (int o = 16; o > 0; o >>= 1) part += __shfl_xor_sync(0xffffffffu, part, o);
    if (lane == 0) red[wid] = part;
    __syncthreads();
    if (tid == 0) {
        float sl = 0.f;
        #pragma unroll
        for (int i = 0; i < 8; i++) sl += red[i];
        int   tl = tgt_lens[b];
        float ls = ls_ptr[0];
        g_params[b] = make_float4(sl / (float)tl, 1.0f / (2.0f * ls * ls), (float)tl, 0.f);
    }
}

__global__ __launch_bounds__(NTH_B)
void lt_main(const float* __restrict__ x,      // (B,S,64)
             const float* __restrict__ mask,   // (B,S)
             float* __restrict__ out_feat,     // (B,T,64)
             float* __restrict__ out_mask,     // (B,T) or null
             int B, int S, int T)
{
    const int b    = blockIdx.y;
    const int t0   = blockIdx.x * TT;
    const int tid  = threadIdx.x;
    const int lane = tid & 31;
    const int wid  = tid >> 5;
    const int tg   = wid * 4;              // first local t of this warp

    // weights, zero-padded 16 front / 16 back per t  (16 x 64 floats = 4 KB)
    __shared__ float wpad[TT][64];

    const float4 p  = g_params[b];
    const float  r  = p.x;
    const float  i2 = p.y;
    const int    tl = (int)p.z;

    // ---- zero this warp's 4 weight rows (64 float4 / 32 lanes = 2 each) ----
    {
        float4* wz = (float4*)&wpad[tg][0];
        wz[lane]      = make_float4(0.f, 0.f, 0.f, 0.f);
        wz[lane + 32] = make_float4(0.f, 0.f, 0.f, 0.f);
    }
    __syncwarp();

    // ---- tgt_mask (4 lanes per warp) ----
    if (out_mask && lane < 4) {
        int t = t0 + tg + lane;
        if (t < T) out_mask[(size_t)b * T + t] = (t < tl) ? 1.0f : 0.0f;
    }

    // ---- per-t windowed softmax; sb computed uniformly by every lane ----
    int sb[4];
    #pragma unroll
    for (int tt = 0; tt < 4; tt++) {
        int t  = min(t0 + tg + tt, T - 1);
        float c = r * (float)t;
        int   s0 = __float2int_rn(c);
        int   w  = s0 - 15;
        w = max(w, 0);  w = min(w, S - 32);
        sb[tt] = w;
        if (t0 + tg + tt < T) {
            int   s   = w + lane;
            float d   = (float)s - c;
            float lg0 = -d * d * i2;
            float m   = mask[(size_t)b * S + s];
            float lg  = m * lg0 - (1.0f - m) * 1e10f;
            float mx  = lg;
            #pragma unroll
            for (int o = 16; o > 0; o >>= 1)
                mx = fmaxf(mx, __shfl_xor_sync(0xffffffffu, mx, o));
            float e  = __expf(lg - mx);
            float sm = e;
            #pragma unroll
            for (int o = 16; o > 0; o >>= 1)
                sm += __shfl_xor_sync(0xffffffffu, sm, o);
            wpad[tg + tt][16 + lane] = e / sm;
        }
    }
    __syncwarp();

    const int ub    = sb[0];
    const int nu    = sb[3] + 32 - ub;        // union window length
    const int delta = sb[3] - sb[0];

    float2 a0 = {0.f, 0.f}, a1 = {0.f, 0.f}, a2 = {0.f, 0.f}, a3 = {0.f, 0.f};
    const float2* __restrict__ xr = (const float2*)(x + ((size_t)b * S + ub) * 64);

    if (delta <= 16 && nu <= 48) {
        // fast union sweep: each row loaded once, 8 FMA into 4 accumulators
        const float* w0p = &wpad[tg + 0][16 + ub - sb[0]];
        const float* w1p = &wpad[tg + 1][16 + ub - sb[1]];
        const float* w2p = &wpad[tg + 2][16 + ub - sb[2]];
        const float* w3p = &wpad[tg + 3][16 + ub - sb[3]];
        #pragma unroll 2
        for (int j = 0; j < nu; j++) {
            float2 xv = xr[j * 32 + lane];
            float  w0 = w0p[j], w1 = w1p[j], w2 = w2p[j], w3 = w3p[j];
            a0.x = fmaf(w0, xv.x, a0.x);  a0.y = fmaf(w0, xv.y, a0.y);
            a1.x = fmaf(w1, xv.x, a1.x);  a1.y = fmaf(w1, xv.y, a1.y);
            a2.x = fmaf(w2, xv.x, a2.x);  a2.y = fmaf(w2, xv.y, a2.y);
            a3.x = fmaf(w3, xv.x, a3.x);  a3.y = fmaf(w3, xv.y, a3.y);
        }
    } else {
        // safety path (huge r): independent 32-row loops per t
        float2* accs[4] = {&a0, &a1, &a2, &a3};
        #pragma unroll
        for (int tt = 0; tt < 4; tt++) {
            const float2* xt = (const float2*)(x + ((size_t)b * S + sb[tt]) * 64);
            float ax = 0.f, ay = 0.f;
            for (int k = 0; k < 32; k++) {
                float  w  = wpad[tg + tt][16 + k];
                float2 xv = xt[k * 32 + lane];
                ax = fmaf(w, xv.x, ax);
                ay = fmaf(w, xv.y, ay);
            }
            accs[tt]->x = ax;  accs[tt]->y = ay;
        }
    }

    // ---- store ----
    float2* o2 = (float2*)(out_feat + ((size_t)b * T + (t0 + tg)) * 64);
    if (t0 + tg + 0 < T) o2[lane]          = a0;
    if (t0 + tg + 1 < T) o2[32 + lane]     = a1;
    if (t0 + tg + 2 < T) o2[64 + lane]     = a2;
    if (t0 + tg + 3 < T) o2[96 + lane]     = a3;
}

// Generic fallback (any D, any S>=32): one warp per (b,t).
__global__ void length_transform_generic(const float* __restrict__ x,
                                         const float* __restrict__ mask,
                                         const float* __restrict__ ls_ptr,
                                         const int*   __restrict__ tgt_lens,
                                         float* __restrict__ out_feat,
                                         float* __restrict__ out_mask,
                                         int B, int S, int T, int D)
{
    int bt = blockIdx.x;
    int b = bt / T, t = bt % T;
    int lane = threadIdx.x;
    __shared__ float wsh[32];

    float part = 0.f;
    for (int i = lane; i < S; i += 32) part += mask[(size_t)b * S + i];
    #pragma unroll
    for (int o = 16; o > 0; o >>= 1) part += __shfl_xor_sync(0xffffffffu, part, o);
    float sl = part;
    int   tl = tgt_lens[b];
    float r  = sl / (float)tl;
    float ls = ls_ptr[0];
    float i2 = 1.f / (2.f * ls * ls);

    float c  = r * (float)t;
    int   s0 = __float2int_rn(c);
    int   sb = min(max(s0 - 15, 0), max(S - 32, 0));
    int   s  = min(sb + lane, S - 1);
    float d  = (float)s - c;
    float lg0 = -d * d * i2;
    float m  = mask[(size_t)b * S + s];
    float lg = m * lg0 - (1.f - m) * 1e10f;
    if (sb + lane > S - 1) lg = -3.0e38f;
    float mx = lg;
    #pragma unroll
    for (int o = 16; o > 0; o >>= 1) mx = fmaxf(mx, __shfl_xor_sync(0xffffffffu, mx, o));
    float e = __expf(lg - mx);
    float sm = e;
    #pragma unroll
    for (int o = 16; o > 0; o >>= 1) sm += __shfl_xor_sync(0xffffffffu, sm, o);
    wsh[lane] = e / sm;
    __syncwarp();

    for (int dd = lane; dd < D; dd += 32) {
        float acc = 0.f;
        for (int k = 0; k < 32; k++) {
            int ss = sb + k;
            if (ss >= S) break;
            acc = fmaf(wsh[k], x[((size_t)b * S + ss) * D + dd], acc);
        }
        out_feat[((size_t)b * T + t) * D + dd] = acc;
    }
    if (out_mask && lane == 0) out_mask[(size_t)b * T + t] = (t < tl) ? 1.f : 0.f;
}

extern "C" void kernel_launch(void* const* d_in, const int* in_sizes, int n_in,
                              void* d_out, int out_size)
{
    const float* x     = (const float*)d_in[0];
    const float* mask  = (const float*)d_in[1];
    const float* ls    = (const float*)d_in[2];
    const int*   tlens = (const int*)d_in[3];

    const int BSD = in_sizes[0];
    const int BS  = in_sizes[1];
    const int B   = in_sizes[3];
    const int D   = BSD / BS;
    const int S   = BS / B;

    long fp1 = (long)B * (D + 1);
    int  T;
    bool has_mask;
    if (out_size % fp1 == 0) { T = (int)(out_size / fp1); has_mask = true; }
    else                     { T = (int)(out_size / ((long)B * D)); has_mask = false; }

    float* ofeat = (float*)d_out;
    float* omask = has_mask ? ofeat + (size_t)B * T * D : nullptr;

    if (D == 64 && S >= 32 && B <= 1024) {
        lt_prep<<<B, 256>>>(mask, ls, tlens, B, S);
        dim3 grid((T + TT - 1) / TT, B);
        lt_main<<<grid, NTH_B>>>(x, mask, ofeat, omask, B, S, T);
    } else {
        length_transform_generic<<<B * T, 32>>>(x, mask, ls, tlens, ofeat, omask, B, S, T, D);
    }
}

// round 3
// speedup vs baseline: 1.2230x; 1.2230x over previous
#include <cuda_runtime.h>
#include <cstdint>

// LengthTransform, round 3: windowed softmax (analytic max, no shuffle-max)
// + fixed-size union sweep with front-batched loads (MLP=8).

#define TT       16    // t-values per block (4 warps x 4 t)
#define NTH_B    128
#define NU       40    // fixed union window rows (holds for r <= ~2.6)

__device__ float4 g_params[1024];   // {r, i2, tl_f, 0} per batch

__global__ void lt_prep(const float* __restrict__ mask,
                        const float* __restrict__ ls_ptr,
                        const int*   __restrict__ tgt_lens,
                        int B, int S)
{
    const int b    = blockIdx.x;
    const int tid  = threadIdx.x;
    const int lane = tid & 31;
    const int wid  = tid >> 5;
    __shared__ float red[8];

    float part = 0.f;
    const int S4 = S >> 2;
    const float4* m4 = (const float4*)(mask + (size_t)b * S);
    for (int i = tid; i < S4; i += 256) {
        float4 v = m4[i];
        part += (v.x + v.y) + (v.z + v.w);
    }
    for (int i = (S4 << 2) + tid; i < S; i += 256) part += mask[(size_t)b * S + i];
    #pragma unroll
    for (int o = 16; o > 0; o >>= 1) part += __shfl_xor_sync(0xffffffffu, part, o);
    if (lane == 0) red[wid] = part;
    __syncthreads();
    if (tid == 0) {
        float sl = 0.f;
        #pragma unroll
        for (int i = 0; i < 8; i++) sl += red[i];
        int   tl = tgt_lens[b];
        float ls = ls_ptr[0];
        g_params[b] = make_float4(sl / (float)tl, 1.0f / (2.0f * ls * ls), (float)tl, 0.f);
    }
}

__global__ __launch_bounds__(NTH_B)
void lt_main(const float* __restrict__ x,      // (B,S,64)
             const float* __restrict__ mask,   // (B,S)
             float* __restrict__ out_feat,     // (B,T,64)
             float* __restrict__ out_mask,     // (B,T) or null
             int B, int S, int T)
{
    const int b    = blockIdx.y;
    const int t0   = blockIdx.x * TT;
    const int tid  = threadIdx.x;
    const int lane = tid & 31;
    const int wid  = tid >> 5;
    const int tg   = wid * 4;

    __shared__ float wpad[TT][64];   // zero-padded weights per t

    const float4 p  = g_params[b];
    const float  r  = p.x;
    const float  i2 = p.y;
    const int    tl = (int)p.z;

    // zero this warp's 4 padded weight rows
    {
        float4* wz = (float4*)&wpad[tg][0];
        wz[lane]      = make_float4(0.f, 0.f, 0.f, 0.f);
        wz[lane + 32] = make_float4(0.f, 0.f, 0.f, 0.f);
    }

    if (out_mask && lane < 4) {
        int t = t0 + tg + lane;
        if (t < T) out_mask[(size_t)b * T + t] = (t < tl) ? 1.0f : 0.0f;
    }
    __syncwarp();

    // ---- phase 1: window bases + mask loads (all 4 in flight) ----
    int   sb[4];
    float cc[4], mv[4];
    #pragma unroll
    for (int tt = 0; tt < 4; tt++) {
        int   t  = min(t0 + tg + tt, T - 1);
        float c  = r * (float)t;
        int   s0 = __float2int_rn(c);
        int   w  = min(max(s0 - 15, 0), S - 32);
        sb[tt] = w;
        cc[tt] = c;
        mv[tt] = mask[(size_t)b * S + w + lane];
    }

    // ---- phase 2: softmax with ANALYTIC max (no shuffle-max) ----
    #pragma unroll
    for (int tt = 0; tt < 4; tt++) {
        float c  = cc[tt];
        int   sn = min(max(__float2int_rn(c), 0), S - 1);   // nearest valid s
        float dm = (float)sn - c;
        float M  = -dm * dm * i2;                            // max unmasked logit
        float d  = (float)(sb[tt] + lane) - c;
        float lg = mv[tt] * (-d * d * i2) - (1.0f - mv[tt]) * 1e10f;
        float e  = __expf(lg - M);
        float sm = e;
        #pragma unroll
        for (int o = 16; o > 0; o >>= 1)
            sm += __shfl_xor_sync(0xffffffffu, sm, o);
        if (t0 + tg + tt < T)
            wpad[tg + tt][16 + lane] = e * __fdividef(1.0f, sm);
    }
    __syncwarp();

    const int ub    = sb[0];
    const int delta = sb[3] - sb[0];

    float2 a0 = {0.f, 0.f}, a1 = {0.f, 0.f}, a2 = {0.f, 0.f}, a3 = {0.f, 0.f};
    const float2* __restrict__ xr = (const float2*)(x + ((size_t)b * S + ub) * 64);

    if (delta <= 8 && ub + NU <= S) {
        // fast path: fixed NU rows, loads front-batched 8 at a time (MLP=8)
        const float* __restrict__ w0p = &wpad[tg + 0][16 + ub - sb[0]];
        const float* __restrict__ w1p = &wpad[tg + 1][16 + ub - sb[1]];
        const float* __restrict__ w2p = &wpad[tg + 2][16 + ub - sb[2]];
        const float* __restrict__ w3p = &wpad[tg + 3][16 + ub - sb[3]];
        #pragma unroll
        for (int c0 = 0; c0 < NU; c0 += 8) {
            float2 xv[8];
            #pragma unroll
            for (int k = 0; k < 8; k++) xv[k] = xr[(c0 + k) * 32 + lane];
            #pragma unroll
            for (int k = 0; k < 8; k++) {
                int   j  = c0 + k;
                float w0 = w0p[j], w1 = w1p[j], w2 = w2p[j], w3 = w3p[j];
                a0.x = fmaf(w0, xv[k].x, a0.x);  a0.y = fmaf(w0, xv[k].y, a0.y);
                a1.x = fmaf(w1, xv[k].x, a1.x);  a1.y = fmaf(w1, xv[k].y, a1.y);
                a2.x = fmaf(w2, xv[k].x, a2.x);  a2.y = fmaf(w2, xv[k].y, a2.y);
                a3.x = fmaf(w3, xv[k].x, a3.x);  a3.y = fmaf(w3, xv[k].y, a3.y);
            }
        }
    } else {
        // boundary / exotic-r path: independent 32-row loops per t
        float2* accs[4] = {&a0, &a1, &a2, &a3};
        #pragma unroll
        for (int tt = 0; tt < 4; tt++) {
            const float2* xt = (const float2*)(x + ((size_t)b * S + sb[tt]) * 64);
            float ax = 0.f, ay = 0.f;
            #pragma unroll 4
            for (int k = 0; k < 32; k++) {
                float  w  = wpad[tg + tt][16 + k];
                float2 xv = xt[k * 32 + lane];
                ax = fmaf(w, xv.x, ax);
                ay = fmaf(w, xv.y, ay);
            }
            accs[tt]->x = ax;  accs[tt]->y = ay;
        }
    }

    float2* o2 = (float2*)(out_feat + ((size_t)b * T + (t0 + tg)) * 64);
    if (t0 + tg + 0 < T) o2[lane]      = a0;
    if (t0 + tg + 1 < T) o2[32 + lane] = a1;
    if (t0 + tg + 2 < T) o2[64 + lane] = a2;
    if (t0 + tg + 3 < T) o2[96 + lane] = a3;
}

// Generic fallback (any D, any S>=32): one warp per (b,t).
__global__ void length_transform_generic(const float* __restrict__ x,
                                         const float* __restrict__ mask,
                                         const float* __restrict__ ls_ptr,
                                         const int*   __restrict__ tgt_lens,
                                         float* __restrict__ out_feat,
                                         float* __restrict__ out_mask,
                                         int B, int S, int T, int D)
{
    int bt = blockIdx.x;
    int b = bt / T, t = bt % T;
    int lane = threadIdx.x;
    __shared__ float wsh[32];

    float part = 0.f;
    for (int i = lane; i < S; i += 32) part += mask[(size_t)b * S + i];
    #pragma unroll
    for (int o = 16; o > 0; o >>= 1) part += __shfl_xor_sync(0xffffffffu, part, o);
    float sl = part;
    int   tl = tgt_lens[b];
    float r  = sl / (float)tl;
    float ls = ls_ptr[0];
    float i2 = 1.f / (2.f * ls * ls);

    float c  = r * (float)t;
    int   s0 = __float2int_rn(c);
    int   sb = min(max(s0 - 15, 0), max(S - 32, 0));
    int   s  = min(sb + lane, S - 1);
    float d  = (float)s - c;
    float lg0 = -d * d * i2;
    float m  = mask[(size_t)b * S + s];
    float lg = m * lg0 - (1.f - m) * 1e10f;
    if (sb + lane > S - 1) lg = -3.0e38f;
    float mx = lg;
    #pragma unroll
    for (int o = 16; o > 0; o >>= 1) mx = fmaxf(mx, __shfl_xor_sync(0xffffffffu, mx, o));
    float e = __expf(lg - mx);
    float sm = e;
    #pragma unroll
    for (int o = 16; o > 0; o >>= 1) sm += __shfl_xor_sync(0xffffffffu, sm, o);
    wsh[lane] = e / sm;
    __syncwarp();

    for (int dd = lane; dd < D; dd += 32) {
        float acc = 0.f;
        for (int k = 0; k < 32; k++) {
            int ss = sb + k;
            if (ss >= S) break;
            acc = fmaf(wsh[k], x[((size_t)b * S + ss) * D + dd], acc);
        }
        out_feat[((size_t)b * T + t) * D + dd] = acc;
    }
    if (out_mask && lane == 0) out_mask[(size_t)b * T + t] = (t < tl) ? 1.f : 0.f;
}

extern "C" void kernel_launch(void* const* d_in, const int* in_sizes, int n_in,
                              void* d_out, int out_size)
{
    const float* x     = (const float*)d_in[0];
    const float* mask  = (const float*)d_in[1];
    const float* ls    = (const float*)d_in[2];
    const int*   tlens = (const int*)d_in[3];

    const int BSD = in_sizes[0];
    const int BS  = in_sizes[1];
    const int B   = in_sizes[3];
    const int D   = BSD / BS;
    const int S   = BS / B;

    long fp1 = (long)B * (D + 1);
    int  T;
    bool has_mask;
    if (out_size % fp1 == 0) { T = (int)(out_size / fp1); has_mask = true; }
    else                     { T = (int)(out_size / ((long)B * D)); has_mask = false; }

    float* ofeat = (float*)d_out;
    float* omask = has_mask ? ofeat + (size_t)B * T * D : nullptr;

    if (D == 64 && S >= 64 && B <= 1024) {
        lt_prep<<<B, 256>>>(mask, ls, tlens, B, S);
        dim3 grid((T + TT - 1) / TT, B);
        lt_main<<<grid, NTH_B>>>(x, mask, ofeat, omask, B, S, T);
    } else {
        length_transform_generic<<<B * T, 32>>>(x, mask, ls, tlens, ofeat, omask, B, S, T, D);
    }
}

// round 4
// speedup vs baseline: 1.3578x; 1.1103x over previous
#include <cuda_runtime.h>
#include <cstdint>

// LengthTransform, round 4: 2 t's/warp, float4 half-warp row split,
// double-buffered union sweep, analytic softmax max.

#define TT       16    // t-values per block (8 warps x 2 t)
#define NTH_B    256
#define NROWS    36    // union window rows (needs 32 + delta, delta<=4)
#define NPAIRS   18    // row pairs
#define CHUNK    6     // pairs per pipeline stage (3 stages)

__device__ float4 g_params[1024];   // {r, i2, tl_f, 0} per batch

__global__ void lt_prep(const float* __restrict__ mask,
                        const float* __restrict__ ls_ptr,
                        const int*   __restrict__ tgt_lens,
                        int B, int S)
{
    const int b    = blockIdx.x;
    const int tid  = threadIdx.x;
    const int lane = tid & 31;
    const int wid  = tid >> 5;
    __shared__ float red[8];

    float part = 0.f;
    const int S4 = S >> 2;
    const float4* m4 = (const float4*)(mask + (size_t)b * S);
    for (int i = tid; i < S4; i += 256) {
        float4 v = m4[i];
        part += (v.x + v.y) + (v.z + v.w);
    }
    for (int i = (S4 << 2) + tid; i < S; i += 256) part += mask[(size_t)b * S + i];
    #pragma unroll
    for (int o = 16; o > 0; o >>= 1) part += __shfl_xor_sync(0xffffffffu, part, o);
    if (lane == 0) red[wid] = part;
    __syncthreads();
    if (tid == 0) {
        float sl = 0.f;
        #pragma unroll
        for (int i = 0; i < 8; i++) sl += red[i];
        int   tl = tgt_lens[b];
        float ls = ls_ptr[0];
        g_params[b] = make_float4(sl / (float)tl, 1.0f / (2.0f * ls * ls), (float)tl, 0.f);
    }
}

__global__ __launch_bounds__(NTH_B)
void lt_main(const float* __restrict__ x,      // (B,S,64)
             const float* __restrict__ mask,   // (B,S)
             float* __restrict__ out_feat,     // (B,T,64)
             float* __restrict__ out_mask,     // (B,T) or null
             int B, int S, int T)
{
    const int b    = blockIdx.y;
    const int t0   = blockIdx.x * TT;
    const int tid  = threadIdx.x;
    const int lane = tid & 31;
    const int wid  = tid >> 5;
    const int tg   = wid * 2;            // first local t of this warp
    const int h    = lane >> 4;          // half-warp id (row parity)

    __shared__ float wpad[TT][64];       // per-t weights, 16-padded both sides

    const float4 p  = g_params[b];
    const float  r  = p.x;
    const float  i2 = p.y;
    const int    tl = (int)p.z;

    // zero this warp's 2 padded weight rows (2*64 floats = 32 float4)
    {
        float4* wz = (float4*)&wpad[tg][0];
        wz[lane] = make_float4(0.f, 0.f, 0.f, 0.f);
    }
    if (out_mask && lane < 2) {
        int t = t0 + tg + lane;
        if (t < T) out_mask[(size_t)b * T + t] = (t < tl) ? 1.0f : 0.0f;
    }
    __syncwarp();

    // ---- windowed softmax, analytic max (no shuffle-max) ----
    int sb[2];
    #pragma unroll
    for (int tt = 0; tt < 2; tt++) {
        int   t  = min(t0 + tg + tt, T - 1);
        float c  = r * (float)t;
        int   s0 = __float2int_rn(c);
        int   w  = min(max(s0 - 15, 0), S - 32);
        sb[tt]   = w;
        float mv = mask[(size_t)b * S + w + lane];
        int   sn = min(max(s0, 0), S - 1);
        float dm = (float)sn - c;
        float M  = -dm * dm * i2;
        float d  = (float)(w + lane) - c;
        float lg = mv * (-d * d * i2) - (1.0f - mv) * 1e10f;
        float e  = __expf(lg - M);
        float sm = e;
        #pragma unroll
        for (int o = 16; o > 0; o >>= 1)
            sm += __shfl_xor_sync(0xffffffffu, sm, o);
        if (t0 + tg + tt < T)
            wpad[tg + tt][16 + lane] = e * __fdividef(1.0f, sm);
    }
    __syncwarp();

    const int ub    = sb[0];
    const int delta = sb[1] - sb[0];

    float4 a0 = {0.f, 0.f, 0.f, 0.f};
    float4 a1 = {0.f, 0.f, 0.f, 0.f};
    const float4* __restrict__ xr4 = (const float4*)(x + ((size_t)b * S + ub) * 64);

    if (delta >= 0 && delta <= 4 && ub + NROWS <= S) {
        // fast path: lane handles row 2*pair+h, D-chunk (lane&15).
        // one LDG.128 per warp covers 2 rows; double-buffered 3x6 pairs.
        const float* __restrict__ w0p = &wpad[tg + 0][16 + ub - sb[0] + h];
        const float* __restrict__ w1p = &wpad[tg + 1][16 + ub - sb[1] + h];
        float4 buf[2][CHUNK];
        #pragma unroll
        for (int k = 0; k < CHUNK; k++) buf[0][k] = xr4[k * 32 + lane];
        #pragma unroll
        for (int c = 0; c < NPAIRS / CHUNK; c++) {
            if (c + 1 < NPAIRS / CHUNK) {
                #pragma unroll
                for (int k = 0; k < CHUNK; k++)
                    buf[(c + 1) & 1][k] = xr4[((c + 1) * CHUNK + k) * 32 + lane];
            }
            #pragma unroll
            for (int k = 0; k < CHUNK; k++) {
                int   j  = (c * CHUNK + k) * 2;       // row index (excl. h)
                float w0 = w0p[j];
                float w1 = w1p[j];
                float4 xv = buf[c & 1][k];
                a0.x = fmaf(w0, xv.x, a0.x);  a0.y = fmaf(w0, xv.y, a0.y);
                a0.z = fmaf(w0, xv.z, a0.z);  a0.w = fmaf(w0, xv.w, a0.w);
                a1.x = fmaf(w1, xv.x, a1.x);  a1.y = fmaf(w1, xv.y, a1.y);
                a1.z = fmaf(w1, xv.z, a1.z);  a1.w = fmaf(w1, xv.w, a1.w);
            }
        }
    } else {
        // boundary path: per-t independent 32-row sweep (16 pairs)
        #pragma unroll
        for (int tt = 0; tt < 2; tt++) {
            const float4* xt4 = (const float4*)(x + ((size_t)b * S + sb[tt]) * 64);
            const float*  wp  = &wpad[tg + tt][16 + h];
            float4 acc = {0.f, 0.f, 0.f, 0.f};
            #pragma unroll 4
            for (int pr = 0; pr < 16; pr++) {
                float4 xv = xt4[pr * 32 + lane];
                float  w  = wp[pr * 2];
                acc.x = fmaf(w, xv.x, acc.x);  acc.y = fmaf(w, xv.y, acc.y);
                acc.z = fmaf(w, xv.z, acc.z);  acc.w = fmaf(w, xv.w, acc.w);
            }
            if (tt == 0) a0 = acc; else a1 = acc;
        }
    }

    // combine the two row-halves (butterfly leaves the sum in both halves)
    a0.x += __shfl_xor_sync(0xffffffffu, a0.x, 16);
    a0.y += __shfl_xor_sync(0xffffffffu, a0.y, 16);
    a0.z += __shfl_xor_sync(0xffffffffu, a0.z, 16);
    a0.w += __shfl_xor_sync(0xffffffffu, a0.w, 16);
    a1.x += __shfl_xor_sync(0xffffffffu, a1.x, 16);
    a1.y += __shfl_xor_sync(0xffffffffu, a1.y, 16);
    a1.z += __shfl_xor_sync(0xffffffffu, a1.z, 16);
    a1.w += __shfl_xor_sync(0xffffffffu, a1.w, 16);

    // lanes 0-15 store t (tg+0), lanes 16-31 store t (tg+1): one STG.128
    int    tsel = t0 + tg + h;
    float4 av   = h ? a1 : a0;
    if (tsel < T) {
        float4* o4 = (float4*)(out_feat + ((size_t)b * T + tsel) * 64);
        o4[lane & 15] = av;
    }
}

// Generic fallback (any D, any S>=32): one warp per (b,t).
__global__ void length_transform_generic(const float* __restrict__ x,
                                         const float* __restrict__ mask,
                                         const float* __restrict__ ls_ptr,
                                         const int*   __restrict__ tgt_lens,
                                         float* __restrict__ out_feat,
                                         float* __restrict__ out_mask,
                                         int B, int S, int T, int D)
{
    int bt = blockIdx.x;
    int b = bt / T, t = bt % T;
    int lane = threadIdx.x;
    __shared__ float wsh[32];

    float part = 0.f;
    for (int i = lane; i < S; i += 32) part += mask[(size_t)b * S + i];
    #pragma unroll
    for (int o = 16; o > 0; o >>= 1) part += __shfl_xor_sync(0xffffffffu, part, o);
    float sl = part;
    int   tl = tgt_lens[b];
    float r  = sl / (float)tl;
    float ls = ls_ptr[0];
    float i2 = 1.f / (2.f * ls * ls);

    float c  = r * (float)t;
    int   s0 = __float2int_rn(c);
    int   sb = min(max(s0 - 15, 0), max(S - 32, 0));
    int   s  = min(sb + lane, S - 1);
    float d  = (float)s - c;
    float lg0 = -d * d * i2;
    float m  = mask[(size_t)b * S + s];
    float lg = m * lg0 - (1.f - m) * 1e10f;
    if (sb + lane > S - 1) lg = -3.0e38f;
    float mx = lg;
    #pragma unroll
    for (int o = 16; o > 0; o >>= 1) mx = fmaxf(mx, __shfl_xor_sync(0xffffffffu, mx, o));
    float e = __expf(lg - mx);
    float sm = e;
    #pragma unroll
    for (int o = 16; o > 0; o >>= 1) sm += __shfl_xor_sync(0xffffffffu, sm, o);
    wsh[lane] = e / sm;
    __syncwarp();

    for (int dd = lane; dd < D; dd += 32) {
        float acc = 0.f;
        for (int k = 0; k < 32; k++) {
            int ss = sb + k;
            if (ss >= S) break;
            acc = fmaf(wsh[k], x[((size_t)b * S + ss) * D + dd], acc);
        }
        out_feat[((size_t)b * T + t) * D + dd] = acc;
    }
    if (out_mask && lane == 0) out_mask[(size_t)b * T + t] = (t < tl) ? 1.f : 0.f;
}

extern "C" void kernel_launch(void* const* d_in, const int* in_sizes, int n_in,
                              void* d_out, int out_size)
{
    const float* x     = (const float*)d_in[0];
    const float* mask  = (const float*)d_in[1];
    const float* ls    = (const float*)d_in[2];
    const int*   tlens = (const int*)d_in[3];

    const int BSD = in_sizes[0];
    const int BS  = in_sizes[1];
    const int B   = in_sizes[3];
    const int D   = BSD / BS;
    const int S   = BS / B;

    long fp1 = (long)B * (D + 1);
    int  T;
    bool has_mask;
    if (out_size % fp1 == 0) { T = (int)(out_size / fp1); has_mask = true; }
    else                     { T = (int)(out_size / ((long)B * D)); has_mask = false; }

    float* ofeat = (float*)d_out;
    float* omask = has_mask ? ofeat + (size_t)B * T * D : nullptr;

    if (D == 64 && S >= 64 && B <= 1024) {
        lt_prep<<<B, 256>>>(mask, ls, tlens, B, S);
        dim3 grid((T + TT - 1) / TT, B);
        lt_main<<<grid, NTH_B>>>(x, mask, ofeat, omask, B, S, T);
    } else {
        length_transform_generic<<<B * T, 32>>>(x, mask, ls, tlens, ofeat, omask, B, S, T, D);
    }
}